// round 7
// baseline (speedup 1.0000x reference)
#include <cuda_runtime.h>
#include <cuda_bf16.h>
#include <stdint.h>

typedef unsigned long long ull;

#define NROWS   65536
#define DDIM    256
#define NCODES  512
#define PCOLS   768
#define TM      64
#define TN      64
#define NTILES  12           // 768 / 64 : tiles 0..7 scores, 8..11 z
#define LDA     264          // padded row stride (bf16) for conflict-free ldmatrix

// k1 smem layout (bytes)
#define A_OFF      0
#define A_BYTES    (TM*LDA*2)                   // 33792
#define P_OFF      A_BYTES
#define PBUF_BYTES (TN*LDA*2)                   // 33792
#define HN_OFF     (A_BYTES + 2*PBUF_BYTES)     // 101376
#define RK_OFF     (HN_OFF + NCODES*4)          // 103424
#define ZQ_OFF     (RK_OFF + TM*8)              // 103936
#define SMEM_TOTAL (ZQ_OFF + TM*4)              // 104192  -> 2 CTAs/SM

__device__ __align__(16) __nv_bfloat16 g_P[PCOLS*DDIM];
__device__ __align__(16) float g_Cout[NCODES*DDIM];
__device__ float g_halfnorm[NCODES];
__device__ float g_adj_acc;
__device__ float g_zsq_acc;

// ---------------------------------------------------------------- K0: preprocessing
__global__ __launch_bounds__(512)
void k0_prep(const float* __restrict__ cb, const float* __restrict__ Win,
             const float* __restrict__ Wout) {
    __shared__ float cbs[4][DDIM];
    __shared__ float ws[8448];
    int b = blockIdx.x, tid = threadIdx.x;

    if (b < 128) {
        // M = cb @ Win, 4 codes/block. thread = (code-pair g, d)
        int c0 = b * 4, g = tid >> 8, d = tid & 255;
        for (int i = tid; i < 4 * DDIM; i += 512) cbs[i >> 8][i & 255] = cb[c0 * DDIM + i];
        float a0 = 0.f, a1 = 0.f;
        for (int e0 = 0; e0 < DDIM; e0 += 32) {
            __syncthreads();
            for (int i = tid; i < 32 * 256; i += 512) {
                int ee = i >> 8, dd = i & 255;
                ws[ee * 257 + dd] = Win[(e0 + ee) * DDIM + dd];
            }
            __syncthreads();
            #pragma unroll
            for (int ee = 0; ee < 32; ee++) {
                float wv = ws[ee * 257 + d];
                a0 += cbs[2 * g + 0][e0 + ee] * wv;
                a1 += cbs[2 * g + 1][e0 + ee] * wv;
            }
        }
        g_P[(c0 + 2 * g + 0) * DDIM + d] = __float2bfloat16(a0);
        g_P[(c0 + 2 * g + 1) * DDIM + d] = __float2bfloat16(a1);
        int wj = tid >> 5, ln = tid & 31;
        if (wj < 4) {
            float s = 0.f;
            for (int e = ln; e < DDIM; e += 32) { float x = cbs[wj][e]; s += x * x; }
            #pragma unroll
            for (int o = 16; o; o >>= 1) s += __shfl_xor_sync(0xffffffffu, s, o);
            if (ln == 0) g_halfnorm[c0 + wj] = 0.5f * s;
        }
    } else if (b < 256) {
        // Cout[c,e] = sum_d cb[c,d]*Wout[e,d], 4 codes/block. thread = (code-pair g, e)
        int c0 = (b - 128) * 4, g = tid >> 8, e = tid & 255;
        for (int i = tid; i < 4 * DDIM; i += 512) cbs[i >> 8][i & 255] = cb[c0 * DDIM + i];
        float a0 = 0.f, a1 = 0.f;
        for (int d0 = 0; d0 < DDIM; d0 += 32) {
            __syncthreads();
            for (int i = tid; i < 256 * 32; i += 512) {
                int ee = i >> 5, dd = i & 31;
                ws[ee * 33 + dd] = Wout[ee * DDIM + d0 + dd];
            }
            __syncthreads();
            #pragma unroll
            for (int dd = 0; dd < 32; dd++) {
                float wv = ws[e * 33 + dd];
                a0 += cbs[2 * g + 0][d0 + dd] * wv;
                a1 += cbs[2 * g + 1][d0 + dd] * wv;
            }
        }
        g_Cout[(c0 + 2 * g + 0) * DDIM + e] = a0;
        g_Cout[(c0 + 2 * g + 1) * DDIM + e] = a1;
    } else {
        // blocks 256..287: Win rows -> P rows 512..767 (bf16)
        int e0 = (b - 256) * 8;
        for (int i = tid; i < 8 * 256; i += 512) {
            int e = e0 + (i >> 8), d = i & 255;
            g_P[(NCODES + e) * DDIM + d] = __float2bfloat16(Win[(size_t)e * DDIM + d]);
        }
        if (b == 256 && tid == 0) { g_adj_acc = 0.f; g_zsq_acc = 0.f; }
    }
}

// ---------------------------------------------------------------- helpers
__device__ __forceinline__ void ldsm4(uint32_t& r0, uint32_t& r1, uint32_t& r2, uint32_t& r3,
                                      uint32_t addr) {
    asm volatile("ldmatrix.sync.aligned.m8n8.x4.shared.b16 {%0,%1,%2,%3},[%4];\n"
                 : "=r"(r0), "=r"(r1), "=r"(r2), "=r"(r3) : "r"(addr));
}
__device__ __forceinline__ void mma16816(float* c, const uint32_t* a, const uint32_t* b) {
    asm volatile("mma.sync.aligned.m16n8k16.row.col.f32.bf16.bf16.f32 "
                 "{%0,%1,%2,%3},{%4,%5,%6,%7},{%8,%9},{%0,%1,%2,%3};\n"
                 : "+f"(c[0]), "+f"(c[1]), "+f"(c[2]), "+f"(c[3])
                 : "r"(a[0]), "r"(a[1]), "r"(a[2]), "r"(a[3]), "r"(b[0]), "r"(b[1]));
}
__device__ __forceinline__ void cp16(uint32_t dst, const void* src) {
    asm volatile("cp.async.cg.shared.global [%0],[%1],16;\n" :: "r"(dst), "l"(src));
}
__device__ __forceinline__ uint32_t fenc(float f) {
    uint32_t s = __float_as_uint(f);
    return (s & 0x80000000u) ? ~s : (s | 0x80000000u);
}

// ---------------------------------------------------------------- K1: main fused kernel
// TM=64 x TN=64 CTA tile, 8 warps (grid 2x4), warp tile 32x16, 2 CTAs/SM.
__global__ __launch_bounds__(256, 2)
void k1_main(const float* __restrict__ hidden, const unsigned char* __restrict__ mask,
             const float* __restrict__ gamma, const float* __restrict__ beta,
             float* __restrict__ dout) {
    extern __shared__ char sm[];
    float* hn     = (float*)(sm + HN_OFF);
    ull*   rowkey = (ull*)  (sm + RK_OFF);
    float* zsq    = (float*)(sm + ZQ_OFF);
    uint32_t sbase = (uint32_t)__cvta_generic_to_shared(sm);

    const int tid = threadIdx.x;
    const int lane = tid & 31, w = tid >> 5;
    const int wr = w >> 2, wc = w & 3;       // 2x4 warp grid
    const int row0 = blockIdx.x << 6;

    if (tid < TM) { rowkey[tid] = 0ull; zsq[tid] = 0.f; }
    for (int i = tid; i < NCODES; i += 256) hn[i] = g_halfnorm[i];

    // A tile: hidden fp32 -> bf16 smem (padded rows)
    for (int i = tid; i < TM * 64; i += 256) {
        int r = i >> 6, c4 = i & 63;
        float4 h4 = *(const float4*)(hidden + (((size_t)(row0 + r)) << 8) + (c4 << 2));
        __nv_bfloat162 p0 = __floats2bfloat162_rn(h4.x, h4.y);
        __nv_bfloat162 p1 = __floats2bfloat162_rn(h4.z, h4.w);
        __nv_bfloat162* dst = (__nv_bfloat162*)(sm + ((r * LDA + (c4 << 2)) << 1));
        dst[0] = p0; dst[1] = p1;
    }

    // prefetch P tile 0
    for (int i = tid; i < TN * 32; i += 256) {
        int c = i >> 5, ch = i & 31;
        uint32_t dst = sbase + P_OFF + ((c * LDA + (ch << 3)) << 1);
        cp16(dst, g_P + (((size_t)c) << 8) + (ch << 3));
    }
    asm volatile("cp.async.commit_group;\n");

    for (int t = 0; t < NTILES; t++) {
        if (t < NTILES - 1) {
            int buf = (t + 1) & 1;
            for (int i = tid; i < TN * 32; i += 256) {
                int c = i >> 5, ch = i & 31;
                uint32_t dst = sbase + P_OFF + buf * PBUF_BYTES + ((c * LDA + (ch << 3)) << 1);
                cp16(dst, g_P + (((size_t)((t + 1) * TN + c)) << 8) + (ch << 3));
            }
            asm volatile("cp.async.commit_group;\n");
            asm volatile("cp.async.wait_group 1;\n");
        } else {
            asm volatile("cp.async.wait_group 0;\n");
        }
        __syncthreads();

        float acc[2][2][4];
        #pragma unroll
        for (int i = 0; i < 2; i++)
            #pragma unroll
            for (int j = 0; j < 2; j++)
                #pragma unroll
                for (int r = 0; r < 4; r++) acc[i][j][r] = 0.f;

        const uint32_t pB = sbase + P_OFF + (t & 1) * PBUF_BYTES;
        #pragma unroll
        for (int k = 0; k < 16; k++) {
            uint32_t a[2][4];
            #pragma unroll
            for (int i = 0; i < 2; i++) {
                int arow = wr * 32 + i * 16 + (lane & 15);
                uint32_t addr = sbase + ((arow * LDA + k * 16 + ((lane >> 4) << 3)) << 1);
                ldsm4(a[i][0], a[i][1], a[i][2], a[i][3], addr);
            }
            uint32_t b[2][2];
            {
                int nrow = wc * 16 + ((lane >> 4) << 3) + (lane & 7);
                int kh = (lane & 15) >> 3;
                uint32_t addr = pB + ((nrow * LDA + k * 16 + kh * 8) << 1);
                uint32_t r0, r1, r2, r3;
                ldsm4(r0, r1, r2, r3, addr);
                b[0][0] = r0; b[0][1] = r1;
                b[1][0] = r2; b[1][1] = r3;
            }
            #pragma unroll
            for (int i = 0; i < 2; i++)
                #pragma unroll
                for (int jn = 0; jn < 2; jn++)
                    mma16816(acc[i][jn], a[i], b[jn]);
        }

        if (t < 8) {
            // score tiles: per-row running (max adj, idx)
            #pragma unroll
            for (int i = 0; i < 2; i++)
                #pragma unroll
                for (int rh = 0; rh < 2; rh++) {
                    int rrow = wr * 32 + i * 16 + rh * 8 + (lane >> 2);
                    ull best = 0ull;
                    #pragma unroll
                    for (int jn = 0; jn < 2; jn++)
                        #pragma unroll
                        for (int b2 = 0; b2 < 2; b2++) {
                            int col = wc * 16 + jn * 8 + ((lane & 3) << 1) + b2;
                            int code = t * TN + col;
                            float adj = acc[i][jn][rh * 2 + b2] - hn[code];
                            ull key = (((ull)fenc(adj)) << 32) |
                                      (uint32_t)(0xFFFFFFFFu - (uint32_t)code);
                            best = (key > best) ? key : best;
                        }
                    ull o1 = __shfl_xor_sync(0xffffffffu, best, 1); best = (o1 > best) ? o1 : best;
                    ull o2 = __shfl_xor_sync(0xffffffffu, best, 2); best = (o2 > best) ? o2 : best;
                    if ((lane & 3) == 0) atomicMax(&rowkey[rrow], best);
                }
        } else {
            // z tiles: ||z||^2 accumulation (exact, all rows)
            #pragma unroll
            for (int i = 0; i < 2; i++)
                #pragma unroll
                for (int rh = 0; rh < 2; rh++) {
                    int rrow = wr * 32 + i * 16 + rh * 8 + (lane >> 2);
                    float s = 0.f;
                    #pragma unroll
                    for (int jn = 0; jn < 2; jn++)
                        #pragma unroll
                        for (int b2 = 0; b2 < 2; b2++) {
                            float v = acc[i][jn][rh * 2 + b2];
                            s += v * v;
                        }
                    s += __shfl_xor_sync(0xffffffffu, s, 1);
                    s += __shfl_xor_sync(0xffffffffu, s, 2);
                    if ((lane & 3) == 0) atomicAdd(&zsq[rrow], s);
                }
        }
        __syncthreads();
    }

    // final epilogue: gather C_out[idx], masked residual, LayerNorm, loss terms
    float adjacc = 0.f, zacc = 0.f;
    #pragma unroll
    for (int rr = 0; rr < 8; rr++) {
        int row = (w << 3) + rr;
        int grow = row0 + row;
        ull key = rowkey[row];
        uint32_t ua = (uint32_t)(key >> 32);
        float adj = (ua & 0x80000000u) ? __uint_as_float(ua & 0x7fffffffu)
                                       : __uint_as_float(~ua);
        int idx = (int)(0xFFFFFFFFu - (uint32_t)(key & 0xFFFFFFFFull));
        if (lane == 0) { adjacc += adj; zacc += zsq[row]; }

        float m = mask[grow] ? 1.0f : 0.0f;
        const float4* hp = (const float4*)(hidden + (((size_t)grow) << 8));
        const float4* op = (const float4*)(g_Cout + (((size_t)idx) << 8));
        float4 h1 = hp[lane], h2 = hp[lane + 32];
        float4 o1 = op[lane], o2 = op[lane + 32];
        float v[8] = { h1.x + m * o1.x, h1.y + m * o1.y, h1.z + m * o1.z, h1.w + m * o1.w,
                       h2.x + m * o2.x, h2.y + m * o2.y, h2.z + m * o2.z, h2.w + m * o2.w };
        float s = 0.f;
        #pragma unroll
        for (int j = 0; j < 8; j++) s += v[j];
        #pragma unroll
        for (int o = 16; o; o >>= 1) s += __shfl_xor_sync(0xffffffffu, s, o);
        float mu = s * (1.f / 256.f);
        float q = 0.f;
        #pragma unroll
        for (int j = 0; j < 8; j++) { float d = v[j] - mu; q += d * d; }
        #pragma unroll
        for (int o = 16; o; o >>= 1) q += __shfl_xor_sync(0xffffffffu, q, o);
        float rstd = rsqrtf(q * (1.f / 256.f) + 1e-5f);

        const float4* gp = (const float4*)gamma;
        const float4* bp = (const float4*)beta;
        float4 g1 = gp[lane], g2 = gp[lane + 32];
        float4 b1 = bp[lane], b2 = bp[lane + 32];
        float4 oA, oB;
        oA.x = (v[0] - mu) * rstd * g1.x + b1.x;
        oA.y = (v[1] - mu) * rstd * g1.y + b1.y;
        oA.z = (v[2] - mu) * rstd * g1.z + b1.z;
        oA.w = (v[3] - mu) * rstd * g1.w + b1.w;
        oB.x = (v[4] - mu) * rstd * g2.x + b2.x;
        oB.y = (v[5] - mu) * rstd * g2.y + b2.y;
        oB.z = (v[6] - mu) * rstd * g2.z + b2.z;
        oB.w = (v[7] - mu) * rstd * g2.w + b2.w;
        float4* dp = (float4*)(dout + (((size_t)grow) << 8));
        dp[lane] = oA; dp[lane + 32] = oB;
    }
    if (lane == 0) {
        atomicAdd(&g_adj_acc, adjacc);
        atomicAdd(&g_zsq_acc, zacc);
    }
}

// ---------------------------------------------------------------- K2: loss finalize (exact)
__global__ void k2_loss(float* dout, int outsize) {
    float num = g_zsq_acc - 2.f * g_adj_acc;
    float loss = 1.25f * num / (float)((size_t)NROWS * DDIM);
    for (int i = NROWS * DDIM + (int)threadIdx.x; i < outsize; i += (int)blockDim.x)
        dout[i] = loss;
}

// ---------------------------------------------------------------- launch
extern "C" void kernel_launch(void* const* d_in, const int* in_sizes, int n_in,
                              void* d_out, int out_size) {
    const float*         hidden = (const float*)d_in[0];
    const unsigned char* mask   = (const unsigned char*)d_in[1];
    const float*         cb     = (const float*)d_in[2];
    const float*         Win    = (const float*)d_in[3];
    const float*         Wout   = (const float*)d_in[4];
    const float*         gamma  = (const float*)d_in[5];
    const float*         beta   = (const float*)d_in[6];
    float* out = (float*)d_out;

    cudaFuncSetAttribute(k1_main, cudaFuncAttributeMaxDynamicSharedMemorySize, SMEM_TOTAL);

    k0_prep<<<288, 512>>>(cb, Win, Wout);
    k1_main<<<NROWS / TM, 256, SMEM_TOTAL>>>(hidden, mask, gamma, beta, out);
    k2_loss<<<1, 32>>>(out, out_size);
}

// round 8
// speedup vs baseline: 1.1098x; 1.1098x over previous
#include <cuda_runtime.h>
#include <cuda_fp16.h>
#include <stdint.h>

typedef unsigned long long ull;

#define NROWS   65536
#define DDIM    256
#define NCODES  512
#define PCOLS   768
#define TM      128
#define TN      128
#define NTILES  6            // 768 / 128 : tiles 0..3 scores, 4..5 z
#define LDA     264          // padded row stride (halfs) for conflict-free ldmatrix

// k1 smem layout (bytes)
#define A_OFF      0
#define A_BYTES    (TM*LDA*2)            // 67584
#define P_OFF      A_BYTES
#define PBUF_BYTES (TN*LDA*2)            // 67584
#define HN_OFF     (A_BYTES + 2*PBUF_BYTES)      // 202752
#define RK_OFF     (HN_OFF + NCODES*4)           // 204800
#define ZQ_OFF     (RK_OFF + TM*8)               // 205824
#define SMEM_TOTAL (ZQ_OFF + TM*4)               // 206336

#define K0_WS_FLOATS 33024                        // max(128*257, 256*129)
#define K0_SMEM      (K0_WS_FLOATS*4)

__device__ __align__(16) __half g_P[PCOLS*DDIM];  // rows 0..511 = cb@Win, 512..767 = Win (fp16)
__device__ __align__(16) float g_Cout[NCODES*DDIM];
__device__ float g_halfnorm[NCODES];
__device__ float g_adj_acc;
__device__ float g_zsq_acc;

// ---------------------------------------------------------------- K0: preprocessing
// 128-row staged chunks in 132KB dynamic smem: 2 chunks, 4 syncs, fully coalesced.
__global__ __launch_bounds__(512)
void k0_prep(const float* __restrict__ cb, const float* __restrict__ Win,
             const float* __restrict__ Wout) {
    extern __shared__ float ws[];
    __shared__ float cbs[4][DDIM];
    int b = blockIdx.x, tid = threadIdx.x;

    if (b < 128) {
        // M = cb @ Win, 4 codes/block. thread = (code-pair g, d); chunk over e (K)
        int c0 = b * 4, g = tid >> 8, d = tid & 255;
        for (int i = tid; i < 4 * DDIM; i += 512) cbs[i >> 8][i & 255] = cb[c0 * DDIM + i];
        float a0 = 0.f, a1 = 0.f;
        for (int e0 = 0; e0 < DDIM; e0 += 128) {
            __syncthreads();
            for (int i = tid; i < 128 * 64; i += 512) {           // 128 rows x 64 float4
                int ee = i >> 6, c4 = (i & 63) << 2;
                float4 v = *(const float4*)(Win + (size_t)(e0 + ee) * DDIM + c4);
                float* w = ws + ee * 257 + c4;
                w[0] = v.x; w[1] = v.y; w[2] = v.z; w[3] = v.w;
            }
            __syncthreads();
            #pragma unroll 16
            for (int ee = 0; ee < 128; ee++) {
                float wv = ws[ee * 257 + d];
                a0 += cbs[2 * g + 0][e0 + ee] * wv;
                a1 += cbs[2 * g + 1][e0 + ee] * wv;
            }
        }
        g_P[(c0 + 2 * g + 0) * DDIM + d] = __float2half_rn(a0);
        g_P[(c0 + 2 * g + 1) * DDIM + d] = __float2half_rn(a1);
        int wj = tid >> 5, ln = tid & 31;
        if (wj < 4) {
            float s = 0.f;
            for (int e = ln; e < DDIM; e += 32) { float x = cbs[wj][e]; s += x * x; }
            #pragma unroll
            for (int o = 16; o; o >>= 1) s += __shfl_xor_sync(0xffffffffu, s, o);
            if (ln == 0) g_halfnorm[c0 + wj] = 0.5f * s;
        }
    } else if (b < 256) {
        // Cout[c,e] = sum_d cb[c,d]*Wout[e,d], 4 codes/block. thread = (g, e); chunk over d
        int c0 = (b - 128) * 4, g = tid >> 8, e = tid & 255;
        for (int i = tid; i < 4 * DDIM; i += 512) cbs[i >> 8][i & 255] = cb[c0 * DDIM + i];
        float a0 = 0.f, a1 = 0.f;
        for (int d0 = 0; d0 < DDIM; d0 += 128) {
            __syncthreads();
            for (int i = tid; i < 256 * 32; i += 512) {           // 256 rows x 32 float4
                int ee = i >> 5, c4 = (i & 31) << 2;
                float4 v = *(const float4*)(Wout + (size_t)ee * DDIM + d0 + c4);
                float* w = ws + ee * 129 + c4;
                w[0] = v.x; w[1] = v.y; w[2] = v.z; w[3] = v.w;
            }
            __syncthreads();
            #pragma unroll 16
            for (int dd = 0; dd < 128; dd++) {
                float wv = ws[e * 129 + dd];
                a0 += cbs[2 * g + 0][d0 + dd] * wv;
                a1 += cbs[2 * g + 1][d0 + dd] * wv;
            }
        }
        g_Cout[(c0 + 2 * g + 0) * DDIM + e] = a0;
        g_Cout[(c0 + 2 * g + 1) * DDIM + e] = a1;
    } else {
        // blocks 256..287: Win rows -> P rows 512..767 (fp16)
        int e0 = (b - 256) * 8;
        for (int i = tid; i < 8 * 256; i += 512) {
            int e = e0 + (i >> 8), d = i & 255;
            g_P[(NCODES + e) * DDIM + d] = __float2half_rn(Win[(size_t)e * DDIM + d]);
        }
        if (b == 256 && tid == 0) { g_adj_acc = 0.f; g_zsq_acc = 0.f; }
    }
}

// ---------------------------------------------------------------- helpers
__device__ __forceinline__ void ldsm4(uint32_t& r0, uint32_t& r1, uint32_t& r2, uint32_t& r3,
                                      uint32_t addr) {
    asm volatile("ldmatrix.sync.aligned.m8n8.x4.shared.b16 {%0,%1,%2,%3},[%4];\n"
                 : "=r"(r0), "=r"(r1), "=r"(r2), "=r"(r3) : "r"(addr));
}
// fp16 inputs, fp16 accumulators (2 x f16x2 regs)
__device__ __forceinline__ void mma16816h(uint32_t* c, const uint32_t* a, const uint32_t* b) {
    asm volatile("mma.sync.aligned.m16n8k16.row.col.f16.f16.f16.f16 "
                 "{%0,%1},{%2,%3,%4,%5},{%6,%7},{%0,%1};\n"
                 : "+r"(c[0]), "+r"(c[1])
                 : "r"(a[0]), "r"(a[1]), "r"(a[2]), "r"(a[3]), "r"(b[0]), "r"(b[1]));
}
__device__ __forceinline__ void cp16(uint32_t dst, const void* src) {
    asm volatile("cp.async.cg.shared.global [%0],[%1],16;\n" :: "r"(dst), "l"(src));
}
__device__ __forceinline__ uint32_t fenc(float f) {
    uint32_t s = __float_as_uint(f);
    return (s & 0x80000000u) ? ~s : (s | 0x80000000u);
}

// ---------------------------------------------------------------- K1: main fused kernel
// 8 warps, warp grid 4x2, warp tile 32x64; f16-accum HMMA.
__global__ __launch_bounds__(256, 1)
void k1_main(const float* __restrict__ hidden, const unsigned char* __restrict__ mask,
             const float* __restrict__ gamma, const float* __restrict__ beta,
             float* __restrict__ dout) {
    extern __shared__ char sm[];
    float* hn     = (float*)(sm + HN_OFF);
    ull*   rowkey = (ull*)  (sm + RK_OFF);
    float* zsq    = (float*)(sm + ZQ_OFF);
    uint32_t sbase = (uint32_t)__cvta_generic_to_shared(sm);

    const int tid = threadIdx.x;
    const int lane = tid & 31, w = tid >> 5;
    const int wr = w >> 1, wc = w & 1;       // 4x2 warp grid
    const int row0 = blockIdx.x << 7;

    if (tid < TM) { rowkey[tid] = 0ull; zsq[tid] = 0.f; }
    for (int i = tid; i < NCODES; i += 256) hn[i] = g_halfnorm[i];

    // A tile: hidden fp32 -> fp16 smem (padded rows)
    for (int i = tid; i < TM * 64; i += 256) {
        int r = i >> 6, c4 = i & 63;
        float4 h4 = *(const float4*)(hidden + (((size_t)(row0 + r)) << 8) + (c4 << 2));
        __half2 p0 = __floats2half2_rn(h4.x, h4.y);
        __half2 p1 = __floats2half2_rn(h4.z, h4.w);
        __half2* dst = (__half2*)(sm + ((r * LDA + (c4 << 2)) << 1));
        dst[0] = p0; dst[1] = p1;
    }

    // prefetch P tile 0
    for (int i = tid; i < TN * 32; i += 256) {
        int c = i >> 5, ch = i & 31;
        uint32_t dst = sbase + P_OFF + ((c * LDA + (ch << 3)) << 1);
        cp16(dst, g_P + (((size_t)c) << 8) + (ch << 3));
    }
    asm volatile("cp.async.commit_group;\n");

    for (int t = 0; t < NTILES; t++) {
        if (t < NTILES - 1) {
            int buf = (t + 1) & 1;
            for (int i = tid; i < TN * 32; i += 256) {
                int c = i >> 5, ch = i & 31;
                uint32_t dst = sbase + P_OFF + buf * PBUF_BYTES + ((c * LDA + (ch << 3)) << 1);
                cp16(dst, g_P + (((size_t)((t + 1) * TN + c)) << 8) + (ch << 3));
            }
            asm volatile("cp.async.commit_group;\n");
            asm volatile("cp.async.wait_group 1;\n");
        } else {
            asm volatile("cp.async.wait_group 0;\n");
        }
        __syncthreads();

        uint32_t acc[2][8][2];                    // f16x2 accumulators
        #pragma unroll
        for (int i = 0; i < 2; i++)
            #pragma unroll
            for (int j = 0; j < 8; j++) { acc[i][j][0] = 0u; acc[i][j][1] = 0u; }

        const uint32_t pB = sbase + P_OFF + (t & 1) * PBUF_BYTES;
        #pragma unroll
        for (int k = 0; k < 16; k++) {
            uint32_t a[2][4];
            #pragma unroll
            for (int i = 0; i < 2; i++) {
                int arow = wr * 32 + i * 16 + (lane & 15);
                uint32_t addr = sbase + ((arow * LDA + k * 16 + ((lane >> 4) << 3)) << 1);
                ldsm4(a[i][0], a[i][1], a[i][2], a[i][3], addr);
            }
            uint32_t b[8][2];
            #pragma unroll
            for (int jj = 0; jj < 4; jj++) {
                int nrow = wc * 64 + jj * 16 + ((lane >> 4) << 3) + (lane & 7);
                int kh = (lane & 15) >> 3;
                uint32_t addr = pB + ((nrow * LDA + k * 16 + kh * 8) << 1);
                uint32_t r0, r1, r2, r3;
                ldsm4(r0, r1, r2, r3, addr);
                b[jj * 2][0] = r0; b[jj * 2][1] = r1;
                b[jj * 2 + 1][0] = r2; b[jj * 2 + 1][1] = r3;
            }
            #pragma unroll
            for (int i = 0; i < 2; i++)
                #pragma unroll
                for (int jn = 0; jn < 8; jn++)
                    mma16816h(acc[i][jn], a[i], b[jn]);
        }

        if (t < 4) {
            // score tiles: per-row running (max adj, idx)
            #pragma unroll
            for (int i = 0; i < 2; i++)
                #pragma unroll
                for (int rh = 0; rh < 2; rh++) {
                    int rrow = wr * 32 + i * 16 + rh * 8 + (lane >> 2);
                    ull best = 0ull;
                    #pragma unroll
                    for (int jn = 0; jn < 8; jn++) {
                        float2 f = __half22float2(*(__half2*)&acc[i][jn][rh]);
                        int col = wc * 64 + jn * 8 + ((lane & 3) << 1);
                        int code = t * TN + col;
                        float adj0 = f.x - hn[code];
                        float adj1 = f.y - hn[code + 1];
                        ull k0v = (((ull)fenc(adj0)) << 32) |
                                  (uint32_t)(0xFFFFFFFFu - (uint32_t)code);
                        ull k1v = (((ull)fenc(adj1)) << 32) |
                                  (uint32_t)(0xFFFFFFFFu - (uint32_t)(code + 1));
                        if (k0v > best) best = k0v;
                        if (k1v > best) best = k1v;
                    }
                    ull o1 = __shfl_xor_sync(0xffffffffu, best, 1); best = (o1 > best) ? o1 : best;
                    ull o2 = __shfl_xor_sync(0xffffffffu, best, 2); best = (o2 > best) ? o2 : best;
                    if ((lane & 3) == 0) atomicMax(&rowkey[rrow], best);
                }
        } else {
            // z tiles: ||z||^2 accumulation (exact, all rows)
            #pragma unroll
            for (int i = 0; i < 2; i++)
                #pragma unroll
                for (int rh = 0; rh < 2; rh++) {
                    int rrow = wr * 32 + i * 16 + rh * 8 + (lane >> 2);
                    float s = 0.f;
                    #pragma unroll
                    for (int jn = 0; jn < 8; jn++) {
                        float2 f = __half22float2(*(__half2*)&acc[i][jn][rh]);
                        s += f.x * f.x + f.y * f.y;
                    }
                    s += __shfl_xor_sync(0xffffffffu, s, 1);
                    s += __shfl_xor_sync(0xffffffffu, s, 2);
                    if ((lane & 3) == 0) atomicAdd(&zsq[rrow], s);
                }
        }
        __syncthreads();
    }

    // final epilogue: gather C_out[idx], masked residual, LayerNorm, loss terms
    float adjacc = 0.f, zacc = 0.f;
    #pragma unroll
    for (int rr = 0; rr < 16; rr++) {
        int row = (w << 4) + rr;
        int grow = row0 + row;
        ull key = rowkey[row];
        uint32_t ua = (uint32_t)(key >> 32);
        float adj = (ua & 0x80000000u) ? __uint_as_float(ua & 0x7fffffffu)
                                       : __uint_as_float(~ua);
        int idx = (int)(0xFFFFFFFFu - (uint32_t)(key & 0xFFFFFFFFull));
        if (lane == 0) { adjacc += adj; zacc += zsq[row]; }

        float m = mask[grow] ? 1.0f : 0.0f;
        const float4* hp = (const float4*)(hidden + (((size_t)grow) << 8));
        const float4* op = (const float4*)(g_Cout + (((size_t)idx) << 8));
        float4 h1 = hp[lane], h2 = hp[lane + 32];
        float4 o1 = op[lane], o2 = op[lane + 32];
        float v[8] = { h1.x + m * o1.x, h1.y + m * o1.y, h1.z + m * o1.z, h1.w + m * o1.w,
                       h2.x + m * o2.x, h2.y + m * o2.y, h2.z + m * o2.z, h2.w + m * o2.w };
        float s = 0.f;
        #pragma unroll
        for (int j = 0; j < 8; j++) s += v[j];
        #pragma unroll
        for (int o = 16; o; o >>= 1) s += __shfl_xor_sync(0xffffffffu, s, o);
        float mu = s * (1.f / 256.f);
        float q = 0.f;
        #pragma unroll
        for (int j = 0; j < 8; j++) { float d = v[j] - mu; q += d * d; }
        #pragma unroll
        for (int o = 16; o; o >>= 1) q += __shfl_xor_sync(0xffffffffu, q, o);
        float rstd = rsqrtf(q * (1.f / 256.f) + 1e-5f);

        const float4* gp = (const float4*)gamma;
        const float4* bp = (const float4*)beta;
        float4 g1 = gp[lane], g2 = gp[lane + 32];
        float4 b1 = bp[lane], b2 = bp[lane + 32];
        float4 oA, oB;
        oA.x = (v[0] - mu) * rstd * g1.x + b1.x;
        oA.y = (v[1] - mu) * rstd * g1.y + b1.y;
        oA.z = (v[2] - mu) * rstd * g1.z + b1.z;
        oA.w = (v[3] - mu) * rstd * g1.w + b1.w;
        oB.x = (v[4] - mu) * rstd * g2.x + b2.x;
        oB.y = (v[5] - mu) * rstd * g2.y + b2.y;
        oB.z = (v[6] - mu) * rstd * g2.z + b2.z;
        oB.w = (v[7] - mu) * rstd * g2.w + b2.w;
        float4* dp = (float4*)(dout + (((size_t)grow) << 8));
        dp[lane] = oA; dp[lane + 32] = oB;
    }
    if (lane == 0) {
        atomicAdd(&g_adj_acc, adjacc);
        atomicAdd(&g_zsq_acc, zacc);
    }
}

// ---------------------------------------------------------------- K2: loss finalize (exact)
__global__ void k2_loss(float* dout, int outsize) {
    float num = g_zsq_acc - 2.f * g_adj_acc;
    float loss = 1.25f * num / (float)((size_t)NROWS * DDIM);
    for (int i = NROWS * DDIM + (int)threadIdx.x; i < outsize; i += (int)blockDim.x)
        dout[i] = loss;
}

// ---------------------------------------------------------------- launch
extern "C" void kernel_launch(void* const* d_in, const int* in_sizes, int n_in,
                              void* d_out, int out_size) {
    const float*         hidden = (const float*)d_in[0];
    const unsigned char* mask   = (const unsigned char*)d_in[1];
    const float*         cb     = (const float*)d_in[2];
    const float*         Win    = (const float*)d_in[3];
    const float*         Wout   = (const float*)d_in[4];
    const float*         gamma  = (const float*)d_in[5];
    const float*         beta   = (const float*)d_in[6];
    float* out = (float*)d_out;

    cudaFuncSetAttribute(k0_prep, cudaFuncAttributeMaxDynamicSharedMemorySize, K0_SMEM);
    cudaFuncSetAttribute(k1_main, cudaFuncAttributeMaxDynamicSharedMemorySize, SMEM_TOTAL);

    k0_prep<<<288, 512, K0_SMEM>>>(cb, Win, Wout);
    k1_main<<<NROWS / TM, 256, SMEM_TOTAL>>>(hidden, mask, gamma, beta, out);
    k2_loss<<<1, 32>>>(out, out_size);
}